// round 1
// baseline (speedup 1.0000x reference)
#include <cuda_runtime.h>
#include <math.h>

// Scratch for intermediate pyramid levels (device globals: no allocation allowed).
__device__ float g_h64 [64 * 64 * 64];
__device__ float g_h128[64 * 128 * 128];
__device__ float g_h256[64 * 256 * 256];

// Keys cubic kernel, a = -0.5 (matches jax.image.resize method='cubic').
__device__ __forceinline__ float keys_w(float d) {
    d = fabsf(d);
    if (d <= 1.0f) return (1.5f * d - 2.5f) * d * d + 1.0f;
    if (d <  2.0f) return ((-0.5f * d + 2.5f) * d - 4.0f) * d + 2.0f;
    return 0.0f;
}

// jax semantics: x = (i+0.5)*in/out - 0.5; taps floor(x)-1 .. floor(x)+2;
// out-of-range taps dropped and the remaining weights renormalized.
template <int SCALE>
__device__ __forceinline__ int cubic_taps(int i, int in_size, float w[4]) {
    const float inv = 1.0f / (float)SCALE;
    float x = ((float)i + 0.5f) * inv - 0.5f;
    int fl = (int)floorf(x);
    int j0 = fl - 1;
    float s = 0.0f;
#pragma unroll
    for (int k = 0; k < 4; k++) {
        int j = j0 + k;
        float wk = keys_w(x - (float)j);
        if (j < 0 || j >= in_size) wk = 0.0f;
        w[k] = wk;
        s += wk;
    }
    float invs = 1.0f / s;
#pragma unroll
    for (int k = 0; k < 4; k++) w[k] *= invs;
    return j0;
}

// Tiled separable bicubic upsample. Optionally fused 1x1 conv (+skip) + ReLU,
// optionally batch-flipped output (final stage).
// TILE = output tile edge; input tile edge = TILE/SCALE + 4 (always 36 here).
template <int SCALE, int TILE, bool FUSE, bool FLIP>
__global__ void __launch_bounds__(256) up_kernel(
    const float* __restrict__ in, int in_size,
    const float* __restrict__ cam,
    const float* __restrict__ wv, const float* __restrict__ bv,
    float* __restrict__ out)
{
    constexpr int IT     = TILE / SCALE + 4;  // 36
    constexpr int RPITCH = IT + 1;            // 37 (odd: conflict-free rows)
    constexpr int HPITCH = TILE + 4;          // keeps 16B row alignment

    __shared__ __align__(16) float raw [IT * RPITCH];
    __shared__ __align__(16) float hmem[IT * HPITCH];

    const int out_size = in_size * SCALE;
    const int tx0 = blockIdx.x * TILE;
    const int ty0 = blockIdx.y * TILE;
    const int b   = blockIdx.z;
    const int in_x0 = tx0 / SCALE - 2;
    const int in_y0 = ty0 / SCALE - 2;
    const int t = threadIdx.x;

    const float* inb = in + (size_t)b * in_size * in_size;

    // ---- load input tile (clamped; clamped taps always have weight 0) ----
    for (int idx = t; idx < IT * IT; idx += 256) {
        int r = idx / IT, c = idx % IT;
        int gr = min(max(in_y0 + r, 0), in_size - 1);
        int gc = min(max(in_x0 + c, 0), in_size - 1);
        raw[r * RPITCH + c] = inb[(size_t)gr * in_size + gc];
    }
    __syncthreads();

    // ---- horizontal pass: IT rows x TILE out-cols ----
    {
        const int c  = t % TILE;
        const int r0 = t / TILE;
        constexpr int RSTEP = 256 / TILE;
        float w[4];
        int j0 = cubic_taps<SCALE>(tx0 + c, in_size, w);
        int jr = j0 - in_x0;  // in [0, IT-4]
        for (int r = r0; r < IT; r += RSTEP) {
            const float* rp = &raw[r * RPITCH + jr];
            hmem[r * HPITCH + c] = w[0]*rp[0] + w[1]*rp[1] + w[2]*rp[2] + w[3]*rp[3];
        }
    }
    __syncthreads();

    // ---- vertical pass + fused epilogue + float4-coalesced store ----
    {
        constexpr int CG       = TILE / 4;   // float4 groups per row
        constexpr int NRB      = 256 / CG;   // row blocks
        constexpr int ROWS_PER = TILE / NRB;
        const int c4 = t % CG;
        const int rb = t / CG;
        const int cc = c4 * 4;

        float fw0 = 0.f, fw1 = 0.f, fb = 0.f;
        if (FUSE) { fw0 = wv[0]; fw1 = wv[1]; fb = bv[0]; }

        float* outb = out + (size_t)(FLIP ? (gridDim.z - 1 - b) : b) * out_size * out_size;

        for (int rr = 0; rr < ROWS_PER; rr++) {
            int r  = rb * ROWS_PER + rr;
            int gr = ty0 + r;
            float wy[4];
            int j0 = cubic_taps<SCALE>(gr, in_size, wy);
            int jr = j0 - in_y0;

            float4 a0 = *(const float4*)&hmem[(jr + 0) * HPITCH + cc];
            float4 a1 = *(const float4*)&hmem[(jr + 1) * HPITCH + cc];
            float4 a2 = *(const float4*)&hmem[(jr + 2) * HPITCH + cc];
            float4 a3 = *(const float4*)&hmem[(jr + 3) * HPITCH + cc];

            float4 v;
            v.x = wy[0]*a0.x + wy[1]*a1.x + wy[2]*a2.x + wy[3]*a3.x;
            v.y = wy[0]*a0.y + wy[1]*a1.y + wy[2]*a2.y + wy[3]*a3.y;
            v.z = wy[0]*a0.z + wy[1]*a1.z + wy[2]*a2.z + wy[3]*a3.z;
            v.w = wy[0]*a0.w + wy[1]*a1.w + wy[2]*a2.w + wy[3]*a3.w;

            if (FUSE) {
                const float4 cm = *(const float4*)&cam[((size_t)b * out_size + gr) * out_size + tx0 + cc];
                v.x = fmaxf(fw0 * v.x + fw1 * cm.x + fb, 0.0f);
                v.y = fmaxf(fw0 * v.y + fw1 * cm.y + fb, 0.0f);
                v.z = fmaxf(fw0 * v.z + fw1 * cm.z + fb, 0.0f);
                v.w = fmaxf(fw0 * v.w + fw1 * cm.w + fb, 0.0f);
            }
            *(float4*)&outb[(size_t)gr * out_size + tx0 + cc] = v;
        }
    }
}

extern "C" void kernel_launch(void* const* d_in, const int* in_sizes, int n_in,
                              void* d_out, int out_size)
{
    (void)in_sizes; (void)n_in; (void)out_size;
    const float* cam256 = (const float*)d_in[0];
    const float* cam128 = (const float*)d_in[1];
    const float* cam64  = (const float*)d_in[2];
    const float* cam32  = (const float*)d_in[3];
    const float* w1 = (const float*)d_in[4];
    const float* b1 = (const float*)d_in[5];
    const float* w2 = (const float*)d_in[6];
    const float* b2 = (const float*)d_in[7];
    const float* w3 = (const float*)d_in[8];
    const float* b3 = (const float*)d_in[9];
    float* out = (float*)d_out;

    float *h64, *h128, *h256;
    cudaGetSymbolAddress((void**)&h64,  g_h64);
    cudaGetSymbolAddress((void**)&h128, g_h128);
    cudaGetSymbolAddress((void**)&h256, g_h256);

    // stage 1: 32 -> 64, fuse cam_64
    up_kernel<2, 64, true, false><<<dim3(1, 1, 64), 256>>>(cam32, 32, cam64, w1, b1, h64);
    // stage 2: 64 -> 128, fuse cam_128
    up_kernel<2, 64, true, false><<<dim3(2, 2, 64), 256>>>(h64, 64, cam128, w2, b2, h128);
    // stage 3: 128 -> 256, fuse cam_256
    up_kernel<2, 64, true, false><<<dim3(4, 4, 64), 256>>>(h128, 128, cam256, w3, b3, h256);
    // stage 4: 256 -> 1024, batch-flipped
    up_kernel<4, 128, false, true><<<dim3(8, 8, 64), 256>>>(h256, 256, nullptr, nullptr, nullptr, out);
}

// round 2
// speedup vs baseline: 1.6393x; 1.6393x over previous
#include <cuda_runtime.h>
#include <math.h>

// Scratch for intermediate pyramid levels (device globals: no allocation allowed).
__device__ float g_h64 [64 * 64 * 64];
__device__ float g_h128[64 * 128 * 128];
__device__ float g_h256[64 * 256 * 256];

// Keys cubic kernel, a = -0.5 (matches jax.image.resize method='cubic').
__device__ __forceinline__ float keys_w(float d) {
    d = fabsf(d);
    if (d <= 1.0f) return (1.5f * d - 2.5f) * d * d + 1.0f;
    if (d <  2.0f) return ((-0.5f * d + 2.5f) * d - 4.0f) * d + 2.0f;
    return 0.0f;
}

// jax semantics: x = (i+0.5)*in/out - 0.5; taps floor(x)-1 .. floor(x)+2;
// out-of-range taps dropped and the remaining weights renormalized.
template <int SCALE>
__device__ __forceinline__ int cubic_taps(int i, int in_size, float w[4]) {
    const float inv = 1.0f / (float)SCALE;
    float x = ((float)i + 0.5f) * inv - 0.5f;
    int fl = (int)floorf(x);
    int j0 = fl - 1;
    float s = 0.0f;
#pragma unroll
    for (int k = 0; k < 4; k++) {
        int j = j0 + k;
        float wk = keys_w(x - (float)j);
        if (j < 0 || j >= in_size) wk = 0.0f;
        w[k] = wk;
        s += wk;
    }
    float invs = 1.0f / s;
#pragma unroll
    for (int k = 0; k < 4; k++) w[k] *= invs;
    return j0;
}

// ======================= scale-2 stages (1-3) ==============================
// Tiled separable bicubic 2x upsample, fused 1x1 conv + ReLU.
template <int TILE>
__global__ void __launch_bounds__(256) up2_kernel(
    const float* __restrict__ in, int in_size,
    const float* __restrict__ cam,
    const float* __restrict__ wv, const float* __restrict__ bv,
    float* __restrict__ out)
{
    constexpr int IT     = TILE / 2 + 4;
    constexpr int RPITCH = IT + 1;
    constexpr int HPITCH = TILE + 4;

    __shared__ __align__(16) float raw [IT * RPITCH];
    __shared__ __align__(16) float hmem[IT * HPITCH];

    const int out_size = in_size * 2;
    const int tx0 = blockIdx.x * TILE;
    const int ty0 = blockIdx.y * TILE;
    const int b   = blockIdx.z;
    const int in_x0 = tx0 / 2 - 2;
    const int in_y0 = ty0 / 2 - 2;
    const int t = threadIdx.x;

    const float* inb = in + (size_t)b * in_size * in_size;

    for (int idx = t; idx < IT * IT; idx += 256) {
        int r = idx / IT, c = idx % IT;
        int gr = min(max(in_y0 + r, 0), in_size - 1);
        int gc = min(max(in_x0 + c, 0), in_size - 1);
        raw[r * RPITCH + c] = inb[(size_t)gr * in_size + gc];
    }
    __syncthreads();

    // horizontal
    {
        const int c  = t % TILE;
        const int r0 = t / TILE;
        constexpr int RSTEP = 256 / TILE;
        float w[4];
        int j0 = cubic_taps<2>(tx0 + c, in_size, w);
        int jr = j0 - in_x0;
        for (int r = r0; r < IT; r += RSTEP) {
            const float* rp = &raw[r * RPITCH + jr];
            hmem[r * HPITCH + c] = w[0]*rp[0] + w[1]*rp[1] + w[2]*rp[2] + w[3]*rp[3];
        }
    }
    __syncthreads();

    // vertical + fused epilogue
    {
        constexpr int CG       = TILE / 4;
        constexpr int NRB      = 256 / CG;
        constexpr int ROWS_PER = TILE / NRB;
        const int c4 = t % CG;
        const int rb = t / CG;
        const int cc = c4 * 4;

        const float fw0 = wv[0], fw1 = wv[1], fb = bv[0];

        float* outb = out + (size_t)b * out_size * out_size;

        for (int rr = 0; rr < ROWS_PER; rr++) {
            int r  = rb * ROWS_PER + rr;
            int gr = ty0 + r;
            float wy[4];
            int j0 = cubic_taps<2>(gr, in_size, wy);
            int jr = j0 - in_y0;

            float4 a0 = *(const float4*)&hmem[(jr + 0) * HPITCH + cc];
            float4 a1 = *(const float4*)&hmem[(jr + 1) * HPITCH + cc];
            float4 a2 = *(const float4*)&hmem[(jr + 2) * HPITCH + cc];
            float4 a3 = *(const float4*)&hmem[(jr + 3) * HPITCH + cc];

            float4 v;
            v.x = wy[0]*a0.x + wy[1]*a1.x + wy[2]*a2.x + wy[3]*a3.x;
            v.y = wy[0]*a0.y + wy[1]*a1.y + wy[2]*a2.y + wy[3]*a3.y;
            v.z = wy[0]*a0.z + wy[1]*a1.z + wy[2]*a2.z + wy[3]*a3.z;
            v.w = wy[0]*a0.w + wy[1]*a1.w + wy[2]*a2.w + wy[3]*a3.w;

            const float4 cm = *(const float4*)&cam[((size_t)b * out_size + gr) * out_size + tx0 + cc];
            v.x = fmaxf(fw0 * v.x + fw1 * cm.x + fb, 0.0f);
            v.y = fmaxf(fw0 * v.y + fw1 * cm.y + fb, 0.0f);
            v.z = fmaxf(fw0 * v.z + fw1 * cm.z + fb, 0.0f);
            v.w = fmaxf(fw0 * v.w + fw1 * cm.w + fb, 0.0f);

            *(float4*)&outb[(size_t)gr * out_size + tx0 + cc] = v;
        }
    }
}

// ======================= stage 4: specialized 4x, flipped ==================
// Key structure for 4x: output rows 4k..4k+3 depend only on input rows
// k-2..k+2 (5 rows), with tap-start offsets fixed per phase (0,0,1,1).
// Weights are precomputed once per block into smem (incl. edge renorm).
__global__ void __launch_bounds__(256) up4_kernel(
    const float* __restrict__ in, float* __restrict__ out)
{
    constexpr int TILE = 128, IN = 256, OUT = 1024;
    constexpr int IT = TILE / 4 + 4;   // 36
    constexpr int RP = IT + 1;         // 37
    constexpr int HP = TILE + 4;       // 132

    __shared__ __align__(16) float  raw [IT * RP];
    __shared__ __align__(16) float  hmem[IT * HP];
    __shared__ __align__(16) float4 wxs[TILE];
    __shared__ __align__(16) float4 wys[TILE];

    const int tx0 = blockIdx.x * TILE;
    const int ty0 = blockIdx.y * TILE;
    const int b   = blockIdx.z;
    const int ix0 = tx0 / 4 - 2;
    const int iy0 = ty0 / 4 - 2;
    const int t = threadIdx.x;

    // ---- precompute per-column / per-row cubic weights (once per block) ----
    {
        float w[4];
        if (t < TILE) {
            cubic_taps<4>(tx0 + t, IN, w);
            wxs[t] = make_float4(w[0], w[1], w[2], w[3]);
        } else {
            int r = t - TILE;
            cubic_taps<4>(ty0 + r, IN, w);
            wys[r] = make_float4(w[0], w[1], w[2], w[3]);
        }
    }

    // ---- load input tile (clamped; clamped taps carry weight 0) ----
    const float* inb = in + (size_t)b * IN * IN;
    for (int idx = t; idx < IT * IT; idx += 256) {
        int r = idx / IT, c = idx % IT;
        int gr = min(max(iy0 + r, 0), IN - 1);
        int gc = min(max(ix0 + c, 0), IN - 1);
        raw[r * RP + c] = inb[gr * IN + gc];
    }
    __syncthreads();

    // ---- horizontal: each thread makes 4 consecutive out-cols from 5 inputs
    {
        const int cg = t & 31;        // column group (4 out cols)
        const int r0 = t >> 5;        // 8 row slots
        const float4 wA = wxs[4*cg+0];
        const float4 wB = wxs[4*cg+1];
        const float4 wC = wxs[4*cg+2];
        const float4 wD = wxs[4*cg+3];
        for (int r = r0; r < IT; r += 8) {
            const float* rp = &raw[r * RP + cg];
            float a0 = rp[0], a1 = rp[1], a2 = rp[2], a3 = rp[3], a4 = rp[4];
            float4 v;
            v.x = wA.x*a0 + wA.y*a1 + wA.z*a2 + wA.w*a3;   // phase 0: taps k-2..k+1
            v.y = wB.x*a0 + wB.y*a1 + wB.z*a2 + wB.w*a3;   // phase 1: taps k-2..k+1
            v.z = wC.x*a1 + wC.y*a2 + wC.z*a3 + wC.w*a4;   // phase 2: taps k-1..k+2
            v.w = wD.x*a1 + wD.y*a2 + wD.z*a3 + wD.w*a4;   // phase 3: taps k-1..k+2
            *(float4*)&hmem[r * HP + 4*cg] = v;
        }
    }
    __syncthreads();

    // ---- vertical: each thread makes a 4-row group from 5 smem rows ----
    {
        const int c4 = t & 31;
        const int g0 = t >> 5;        // 8 group slots, 32 groups total
        const int cc = 4 * c4;
        float* outb = out + (size_t)(gridDim.z - 1 - b) * OUT * OUT;

        for (int g = g0; g < TILE / 4; g += 8) {
            float4 a0 = *(const float4*)&hmem[(g + 0) * HP + cc];
            float4 a1 = *(const float4*)&hmem[(g + 1) * HP + cc];
            float4 a2 = *(const float4*)&hmem[(g + 2) * HP + cc];
            float4 a3 = *(const float4*)&hmem[(g + 3) * HP + cc];
            float4 a4 = *(const float4*)&hmem[(g + 4) * HP + cc];

            const float4 w0 = wys[4*g+0];
            const float4 w1 = wys[4*g+1];
            const float4 w2 = wys[4*g+2];
            const float4 w3 = wys[4*g+3];

            float* op = &outb[(size_t)(ty0 + 4*g) * OUT + tx0 + cc];
            float4 v;

            v.x = w0.x*a0.x + w0.y*a1.x + w0.z*a2.x + w0.w*a3.x;
            v.y = w0.x*a0.y + w0.y*a1.y + w0.z*a2.y + w0.w*a3.y;
            v.z = w0.x*a0.z + w0.y*a1.z + w0.z*a2.z + w0.w*a3.z;
            v.w = w0.x*a0.w + w0.y*a1.w + w0.z*a2.w + w0.w*a3.w;
            __stcs((float4*)op, v);

            v.x = w1.x*a0.x + w1.y*a1.x + w1.z*a2.x + w1.w*a3.x;
            v.y = w1.x*a0.y + w1.y*a1.y + w1.z*a2.y + w1.w*a3.y;
            v.z = w1.x*a0.z + w1.y*a1.z + w1.z*a2.z + w1.w*a3.z;
            v.w = w1.x*a0.w + w1.y*a1.w + w1.z*a2.w + w1.w*a3.w;
            __stcs((float4*)(op + OUT), v);

            v.x = w2.x*a1.x + w2.y*a2.x + w2.z*a3.x + w2.w*a4.x;
            v.y = w2.x*a1.y + w2.y*a2.y + w2.z*a3.y + w2.w*a4.y;
            v.z = w2.x*a1.z + w2.y*a2.z + w2.z*a3.z + w2.w*a4.z;
            v.w = w2.x*a1.w + w2.y*a2.w + w2.z*a3.w + w2.w*a4.w;
            __stcs((float4*)(op + 2 * OUT), v);

            v.x = w3.x*a1.x + w3.y*a2.x + w3.z*a3.x + w3.w*a4.x;
            v.y = w3.x*a1.y + w3.y*a2.y + w3.z*a3.y + w3.w*a4.y;
            v.z = w3.x*a1.z + w3.y*a2.z + w3.z*a3.z + w3.w*a4.z;
            v.w = w3.x*a1.w + w3.y*a2.w + w3.z*a3.w + w3.w*a4.w;
            __stcs((float4*)(op + 3 * OUT), v);
        }
    }
}

extern "C" void kernel_launch(void* const* d_in, const int* in_sizes, int n_in,
                              void* d_out, int out_size)
{
    (void)in_sizes; (void)n_in; (void)out_size;
    const float* cam256 = (const float*)d_in[0];
    const float* cam128 = (const float*)d_in[1];
    const float* cam64  = (const float*)d_in[2];
    const float* cam32  = (const float*)d_in[3];
    const float* w1 = (const float*)d_in[4];
    const float* b1 = (const float*)d_in[5];
    const float* w2 = (const float*)d_in[6];
    const float* b2 = (const float*)d_in[7];
    const float* w3 = (const float*)d_in[8];
    const float* b3 = (const float*)d_in[9];
    float* out = (float*)d_out;

    float *h64, *h128, *h256;
    cudaGetSymbolAddress((void**)&h64,  g_h64);
    cudaGetSymbolAddress((void**)&h128, g_h128);
    cudaGetSymbolAddress((void**)&h256, g_h256);

    // stage 1: 32 -> 64, fuse cam_64   (TILE=32 -> 256 blocks)
    up2_kernel<32><<<dim3(2, 2, 64), 256>>>(cam32, 32, cam64, w1, b1, h64);
    // stage 2: 64 -> 128, fuse cam_128 (TILE=32 -> 1024 blocks)
    up2_kernel<32><<<dim3(4, 4, 64), 256>>>(h64, 64, cam128, w2, b2, h128);
    // stage 3: 128 -> 256, fuse cam_256 (TILE=64 -> 1024 blocks)
    up2_kernel<64><<<dim3(4, 4, 64), 256>>>(h128, 128, cam256, w3, b3, h256);
    // stage 4: 256 -> 1024, batch-flipped, specialized 4x
    up4_kernel<<<dim3(8, 8, 64), 256>>>(h256, out);
}

// round 3
// speedup vs baseline: 1.6975x; 1.0355x over previous
#include <cuda_runtime.h>
#include <math.h>

// Scratch for intermediate pyramid levels (device globals: no allocation allowed).
__device__ float g_h64 [64 * 64 * 64];
__device__ float g_h128[64 * 128 * 128];
__device__ float g_h256[64 * 256 * 256];

// Keys cubic kernel, a = -0.5 (matches jax.image.resize method='cubic').
__device__ __forceinline__ float keys_w(float d) {
    d = fabsf(d);
    if (d <= 1.0f) return (1.5f * d - 2.5f) * d * d + 1.0f;
    if (d <  2.0f) return ((-0.5f * d + 2.5f) * d - 4.0f) * d + 2.0f;
    return 0.0f;
}

// jax semantics: x = (i+0.5)*in/out - 0.5; taps floor(x)-1 .. floor(x)+2;
// out-of-range taps dropped and the remaining weights renormalized.
template <int SCALE>
__device__ __forceinline__ int cubic_taps(int i, int in_size, float w[4]) {
    const float inv = 1.0f / (float)SCALE;
    float x = ((float)i + 0.5f) * inv - 0.5f;
    int fl = (int)floorf(x);
    int j0 = fl - 1;
    float s = 0.0f;
#pragma unroll
    for (int k = 0; k < 4; k++) {
        int j = j0 + k;
        float wk = keys_w(x - (float)j);
        if (j < 0 || j >= in_size) wk = 0.0f;
        w[k] = wk;
        s += wk;
    }
    float invs = 1.0f / s;
#pragma unroll
    for (int k = 0; k < 4; k++) w[k] *= invs;
    return j0;
}

// ======================= scale-2 stages (1-3) ==============================
// Tiled separable bicubic 2x upsample, fused 1x1 conv + ReLU.
// All cubic weights/indices precomputed once per block into smem.
template <int TILE>
__global__ void __launch_bounds__(256) up2_kernel(
    const float* __restrict__ in, int in_size,
    const float* __restrict__ cam,
    const float* __restrict__ wv, const float* __restrict__ bv,
    float* __restrict__ out)
{
    constexpr int IT     = TILE / 2 + 4;
    constexpr int RPITCH = IT + 1;
    constexpr int HPITCH = TILE + 4;

    __shared__ __align__(16) float  raw [IT * RPITCH];
    __shared__ __align__(16) float  hmem[IT * HPITCH];
    __shared__ __align__(16) float4 wxs[TILE];
    __shared__ __align__(16) float4 wys[TILE];
    __shared__ int jxs[TILE];
    __shared__ int jys[TILE];

    const int out_size = in_size * 2;
    const int tx0 = blockIdx.x * TILE;
    const int ty0 = blockIdx.y * TILE;
    const int b   = blockIdx.z;
    const int in_x0 = tx0 / 2 - 2;
    const int in_y0 = ty0 / 2 - 2;
    const int t = threadIdx.x;

    // ---- precompute weights + tap indices (once per block) ----
    if (t < TILE) {
        float w[4];
        int j0 = cubic_taps<2>(tx0 + t, in_size, w);
        wxs[t] = make_float4(w[0], w[1], w[2], w[3]);
        jxs[t] = j0 - in_x0;
    } else if (t < 2 * TILE) {
        int r = t - TILE;
        float w[4];
        int j0 = cubic_taps<2>(ty0 + r, in_size, w);
        wys[r] = make_float4(w[0], w[1], w[2], w[3]);
        jys[r] = j0 - in_y0;
    }

    const float* inb = in + (size_t)b * in_size * in_size;
    for (int idx = t; idx < IT * IT; idx += 256) {
        int r = idx / IT, c = idx % IT;
        int gr = min(max(in_y0 + r, 0), in_size - 1);
        int gc = min(max(in_x0 + c, 0), in_size - 1);
        raw[r * RPITCH + c] = inb[(size_t)gr * in_size + gc];
    }
    __syncthreads();

    // horizontal
    {
        const int c  = t % TILE;
        const int r0 = t / TILE;
        constexpr int RSTEP = 256 / TILE;
        const float4 w = wxs[c];
        const int jr = jxs[c];
        for (int r = r0; r < IT; r += RSTEP) {
            const float* rp = &raw[r * RPITCH + jr];
            hmem[r * HPITCH + c] = w.x*rp[0] + w.y*rp[1] + w.z*rp[2] + w.w*rp[3];
        }
    }
    __syncthreads();

    // vertical + fused epilogue
    {
        constexpr int CG       = TILE / 4;
        constexpr int NRB      = 256 / CG;
        constexpr int ROWS_PER = TILE / NRB;
        const int c4 = t % CG;
        const int rb = t / CG;
        const int cc = c4 * 4;

        const float fw0 = wv[0], fw1 = wv[1], fb = bv[0];

        float* outb = out + (size_t)b * out_size * out_size;

        for (int rr = 0; rr < ROWS_PER; rr++) {
            int r  = rb * ROWS_PER + rr;
            int gr = ty0 + r;
            const float4 wy = wys[r];
            const int jr = jys[r];

            float4 a0 = *(const float4*)&hmem[(jr + 0) * HPITCH + cc];
            float4 a1 = *(const float4*)&hmem[(jr + 1) * HPITCH + cc];
            float4 a2 = *(const float4*)&hmem[(jr + 2) * HPITCH + cc];
            float4 a3 = *(const float4*)&hmem[(jr + 3) * HPITCH + cc];

            float4 v;
            v.x = wy.x*a0.x + wy.y*a1.x + wy.z*a2.x + wy.w*a3.x;
            v.y = wy.x*a0.y + wy.y*a1.y + wy.z*a2.y + wy.w*a3.y;
            v.z = wy.x*a0.z + wy.y*a1.z + wy.z*a2.z + wy.w*a3.z;
            v.w = wy.x*a0.w + wy.y*a1.w + wy.z*a2.w + wy.w*a3.w;

            const float4 cm = *(const float4*)&cam[((size_t)b * out_size + gr) * out_size + tx0 + cc];
            v.x = fmaxf(fw0 * v.x + fw1 * cm.x + fb, 0.0f);
            v.y = fmaxf(fw0 * v.y + fw1 * cm.y + fb, 0.0f);
            v.z = fmaxf(fw0 * v.z + fw1 * cm.z + fb, 0.0f);
            v.w = fmaxf(fw0 * v.w + fw1 * cm.w + fb, 0.0f);

            *(float4*)&outb[(size_t)gr * out_size + tx0 + cc] = v;
        }
    }
}

// ======================= stage 4: specialized 4x, flipped ==================
// 4x structure: output rows 4k..4k+3 depend only on input rows k-2..k+2,
// with tap-start offsets fixed per phase (0,0,1,1). Weights precomputed
// per block (incl. edge renorm). High occupancy (8 blocks/SM) is the goal.
__global__ void __launch_bounds__(256, 8) up4_kernel(
    const float* __restrict__ in, float* __restrict__ out)
{
    constexpr int TILE = 128, IN = 256, OUT = 1024;
    constexpr int IT = TILE / 4 + 4;   // 36
    constexpr int RP = IT;             // 36 (all smem accesses are row-internal: pad-free is conflict-free)
    constexpr int HP = TILE;           // 128

    __shared__ __align__(16) float  raw [IT * RP];
    __shared__ __align__(16) float  hmem[IT * HP];
    __shared__ __align__(16) float4 wxs[TILE];
    __shared__ __align__(16) float4 wys[TILE];

    const int tx0 = blockIdx.x * TILE;
    const int ty0 = blockIdx.y * TILE;
    const int b   = blockIdx.z;
    const int ix0 = tx0 / 4 - 2;
    const int iy0 = ty0 / 4 - 2;
    const int t = threadIdx.x;

    // ---- precompute per-column / per-row cubic weights (once per block) ----
    {
        float w[4];
        if (t < TILE) {
            cubic_taps<4>(tx0 + t, IN, w);
            wxs[t] = make_float4(w[0], w[1], w[2], w[3]);
        } else {
            int r = t - TILE;
            cubic_taps<4>(ty0 + r, IN, w);
            wys[r] = make_float4(w[0], w[1], w[2], w[3]);
        }
    }

    // ---- load input tile (clamped; clamped taps carry weight 0) ----
    const float* inb = in + (size_t)b * IN * IN;
    for (int idx = t; idx < IT * IT; idx += 256) {
        int r = idx / IT, c = idx % IT;
        int gr = min(max(iy0 + r, 0), IN - 1);
        int gc = min(max(ix0 + c, 0), IN - 1);
        raw[r * RP + c] = inb[gr * IN + gc];
    }
    __syncthreads();

    // ---- horizontal: each thread makes 4 consecutive out-cols from 5 inputs
    {
        const int cg = t & 31;        // column group (4 out cols)
        const int r0 = t >> 5;        // 8 row slots
        const float4 wA = wxs[4*cg+0];
        const float4 wB = wxs[4*cg+1];
        const float4 wC = wxs[4*cg+2];
        const float4 wD = wxs[4*cg+3];
        for (int r = r0; r < IT; r += 8) {
            const float* rp = &raw[r * RP + cg];
            float a0 = rp[0], a1 = rp[1], a2 = rp[2], a3 = rp[3], a4 = rp[4];
            float4 v;
            v.x = wA.x*a0 + wA.y*a1 + wA.z*a2 + wA.w*a3;   // phase 0: taps k-2..k+1
            v.y = wB.x*a0 + wB.y*a1 + wB.z*a2 + wB.w*a3;   // phase 1: taps k-2..k+1
            v.z = wC.x*a1 + wC.y*a2 + wC.z*a3 + wC.w*a4;   // phase 2: taps k-1..k+2
            v.w = wD.x*a1 + wD.y*a2 + wD.z*a3 + wD.w*a4;   // phase 3: taps k-1..k+2
            *(float4*)&hmem[r * HP + 4*cg] = v;
        }
    }
    __syncthreads();

    // ---- vertical: 4-row group from 5 smem rows; staged to cap live regs ----
    {
        const int c4 = t & 31;
        const int g0 = t >> 5;        // 8 group slots, 32 groups total
        const int cc = 4 * c4;
        float* outb = out + (size_t)(gridDim.z - 1 - b) * OUT * OUT;

        for (int g = g0; g < TILE / 4; g += 8) {
            float* op = &outb[(size_t)(ty0 + 4*g) * OUT + tx0 + cc];

            float4 a0 = *(const float4*)&hmem[(g + 0) * HP + cc];
            float4 a1 = *(const float4*)&hmem[(g + 1) * HP + cc];
            float4 a2 = *(const float4*)&hmem[(g + 2) * HP + cc];
            float4 a3 = *(const float4*)&hmem[(g + 3) * HP + cc];
            float4 v, w;

            w = wys[4*g+0];                       // phase 0: taps g..g+3
            v.x = w.x*a0.x + w.y*a1.x + w.z*a2.x + w.w*a3.x;
            v.y = w.x*a0.y + w.y*a1.y + w.z*a2.y + w.w*a3.y;
            v.z = w.x*a0.z + w.y*a1.z + w.z*a2.z + w.w*a3.z;
            v.w = w.x*a0.w + w.y*a1.w + w.z*a2.w + w.w*a3.w;
            __stcs((float4*)op, v);

            w = wys[4*g+1];                       // phase 1: taps g..g+3
            v.x = w.x*a0.x + w.y*a1.x + w.z*a2.x + w.w*a3.x;
            v.y = w.x*a0.y + w.y*a1.y + w.z*a2.y + w.w*a3.y;
            v.z = w.x*a0.z + w.y*a1.z + w.z*a2.z + w.w*a3.z;
            v.w = w.x*a0.w + w.y*a1.w + w.z*a2.w + w.w*a3.w;
            __stcs((float4*)(op + OUT), v);

            a0 = *(const float4*)&hmem[(g + 4) * HP + cc];  // a0 dead -> reuse for a4

            w = wys[4*g+2];                       // phase 2: taps g+1..g+4
            v.x = w.x*a1.x + w.y*a2.x + w.z*a3.x + w.w*a0.x;
            v.y = w.x*a1.y + w.y*a2.y + w.z*a3.y + w.w*a0.y;
            v.z = w.x*a1.z + w.y*a2.z + w.z*a3.z + w.w*a0.z;
            v.w = w.x*a1.w + w.y*a2.w + w.z*a3.w + w.w*a0.w;
            __stcs((float4*)(op + 2 * OUT), v);

            w = wys[4*g+3];                       // phase 3: taps g+1..g+4
            v.x = w.x*a1.x + w.y*a2.x + w.z*a3.x + w.w*a0.x;
            v.y = w.x*a1.y + w.y*a2.y + w.z*a3.y + w.w*a0.y;
            v.z = w.x*a1.z + w.y*a2.z + w.z*a3.z + w.w*a0.z;
            v.w = w.x*a1.w + w.y*a2.w + w.z*a3.w + w.w*a0.w;
            __stcs((float4*)(op + 3 * OUT), v);
        }
    }
}

extern "C" void kernel_launch(void* const* d_in, const int* in_sizes, int n_in,
                              void* d_out, int out_size)
{
    (void)in_sizes; (void)n_in; (void)out_size;
    const float* cam256 = (const float*)d_in[0];
    const float* cam128 = (const float*)d_in[1];
    const float* cam64  = (const float*)d_in[2];
    const float* cam32  = (const float*)d_in[3];
    const float* w1 = (const float*)d_in[4];
    const float* b1 = (const float*)d_in[5];
    const float* w2 = (const float*)d_in[6];
    const float* b2 = (const float*)d_in[7];
    const float* w3 = (const float*)d_in[8];
    const float* b3 = (const float*)d_in[9];
    float* out = (float*)d_out;

    float *h64, *h128, *h256;
    cudaGetSymbolAddress((void**)&h64,  g_h64);
    cudaGetSymbolAddress((void**)&h128, g_h128);
    cudaGetSymbolAddress((void**)&h256, g_h256);

    // stage 1: 32 -> 64, fuse cam_64   (TILE=32 -> 256 blocks)
    up2_kernel<32><<<dim3(2, 2, 64), 256>>>(cam32, 32, cam64, w1, b1, h64);
    // stage 2: 64 -> 128, fuse cam_128 (TILE=32 -> 1024 blocks)
    up2_kernel<32><<<dim3(4, 4, 64), 256>>>(h64, 64, cam128, w2, b2, h128);
    // stage 3: 128 -> 256, fuse cam_256 (TILE=64 -> 1024 blocks)
    up2_kernel<64><<<dim3(4, 4, 64), 256>>>(h128, 128, cam256, w3, b3, h256);
    // stage 4: 256 -> 1024, batch-flipped, specialized 4x
    up4_kernel<<<dim3(8, 8, 64), 256>>>(h256, out);
}

// round 4
// speedup vs baseline: 1.7775x; 1.0471x over previous
#include <cuda_runtime.h>
#include <math.h>

// Scratch for intermediate pyramid levels (device globals: no allocation allowed).
__device__ float g_h64 [64 * 64 * 64];
__device__ float g_h128[64 * 128 * 128];

// Keys cubic kernel, a = -0.5 (matches jax.image.resize method='cubic').
__device__ __forceinline__ float keys_w(float d) {
    d = fabsf(d);
    if (d <= 1.0f) return (1.5f * d - 2.5f) * d * d + 1.0f;
    if (d <  2.0f) return ((-0.5f * d + 2.5f) * d - 4.0f) * d + 2.0f;
    return 0.0f;
}

// jax semantics: x = (i+0.5)*in/out - 0.5; taps floor(x)-1 .. floor(x)+2;
// out-of-range taps dropped and the remaining weights renormalized.
template <int SCALE>
__device__ __forceinline__ int cubic_taps(int i, int in_size, float w[4]) {
    const float inv = 1.0f / (float)SCALE;
    float x = ((float)i + 0.5f) * inv - 0.5f;
    int fl = (int)floorf(x);
    int j0 = fl - 1;
    float s = 0.0f;
#pragma unroll
    for (int k = 0; k < 4; k++) {
        int j = j0 + k;
        float wk = keys_w(x - (float)j);
        if (j < 0 || j >= in_size) wk = 0.0f;
        w[k] = wk;
        s += wk;
    }
    float invs = 1.0f / s;
#pragma unroll
    for (int k = 0; k < 4; k++) w[k] *= invs;
    return j0;
}

// ======================= scale-2 stages (1-2) ==============================
template <int TILE>
__global__ void __launch_bounds__(256) up2_kernel(
    const float* __restrict__ in, int in_size,
    const float* __restrict__ cam,
    const float* __restrict__ wv, const float* __restrict__ bv,
    float* __restrict__ out)
{
    constexpr int IT     = TILE / 2 + 4;
    constexpr int RPITCH = IT + 1;
    constexpr int HPITCH = TILE + 4;

    __shared__ __align__(16) float  raw [IT * RPITCH];
    __shared__ __align__(16) float  hmem[IT * HPITCH];
    __shared__ __align__(16) float4 wxs[TILE];
    __shared__ __align__(16) float4 wys[TILE];
    __shared__ int jxs[TILE];
    __shared__ int jys[TILE];

    const int out_size = in_size * 2;
    const int tx0 = blockIdx.x * TILE;
    const int ty0 = blockIdx.y * TILE;
    const int b   = blockIdx.z;
    const int in_x0 = tx0 / 2 - 2;
    const int in_y0 = ty0 / 2 - 2;
    const int t = threadIdx.x;

    if (t < TILE) {
        float w[4];
        int j0 = cubic_taps<2>(tx0 + t, in_size, w);
        wxs[t] = make_float4(w[0], w[1], w[2], w[3]);
        jxs[t] = j0 - in_x0;
    } else if (t < 2 * TILE) {
        int r = t - TILE;
        float w[4];
        int j0 = cubic_taps<2>(ty0 + r, in_size, w);
        wys[r] = make_float4(w[0], w[1], w[2], w[3]);
        jys[r] = j0 - in_y0;
    }

    const float* inb = in + (size_t)b * in_size * in_size;
    for (int idx = t; idx < IT * IT; idx += 256) {
        int r = idx / IT, c = idx % IT;
        int gr = min(max(in_y0 + r, 0), in_size - 1);
        int gc = min(max(in_x0 + c, 0), in_size - 1);
        raw[r * RPITCH + c] = inb[(size_t)gr * in_size + gc];
    }
    __syncthreads();

    // horizontal
    {
        const int c  = t % TILE;
        const int r0 = t / TILE;
        constexpr int RSTEP = 256 / TILE;
        const float4 w = wxs[c];
        const int jr = jxs[c];
        for (int r = r0; r < IT; r += RSTEP) {
            const float* rp = &raw[r * RPITCH + jr];
            hmem[r * HPITCH + c] = w.x*rp[0] + w.y*rp[1] + w.z*rp[2] + w.w*rp[3];
        }
    }
    __syncthreads();

    // vertical + fused epilogue
    {
        constexpr int CG       = TILE / 4;
        constexpr int NRB      = 256 / CG;
        constexpr int ROWS_PER = TILE / NRB;
        const int c4 = t % CG;
        const int rb = t / CG;
        const int cc = c4 * 4;

        const float fw0 = wv[0], fw1 = wv[1], fb = bv[0];
        float* outb = out + (size_t)b * out_size * out_size;

        for (int rr = 0; rr < ROWS_PER; rr++) {
            int r  = rb * ROWS_PER + rr;
            int gr = ty0 + r;
            const float4 wy = wys[r];
            const int jr = jys[r];

            float4 a0 = *(const float4*)&hmem[(jr + 0) * HPITCH + cc];
            float4 a1 = *(const float4*)&hmem[(jr + 1) * HPITCH + cc];
            float4 a2 = *(const float4*)&hmem[(jr + 2) * HPITCH + cc];
            float4 a3 = *(const float4*)&hmem[(jr + 3) * HPITCH + cc];

            float4 v;
            v.x = wy.x*a0.x + wy.y*a1.x + wy.z*a2.x + wy.w*a3.x;
            v.y = wy.x*a0.y + wy.y*a1.y + wy.z*a2.y + wy.w*a3.y;
            v.z = wy.x*a0.z + wy.y*a1.z + wy.z*a2.z + wy.w*a3.z;
            v.w = wy.x*a0.w + wy.y*a1.w + wy.z*a2.w + wy.w*a3.w;

            const float4 cm = *(const float4*)&cam[((size_t)b * out_size + gr) * out_size + tx0 + cc];
            v.x = fmaxf(fw0 * v.x + fw1 * cm.x + fb, 0.0f);
            v.y = fmaxf(fw0 * v.y + fw1 * cm.y + fb, 0.0f);
            v.z = fmaxf(fw0 * v.z + fw1 * cm.z + fb, 0.0f);
            v.w = fmaxf(fw0 * v.w + fw1 * cm.w + fb, 0.0f);

            *(float4*)&outb[(size_t)gr * out_size + tx0 + cc] = v;
        }
    }
}

// ================= fused stage 3 (2x + conv/ReLU) + stage 4 (4x, flip) =====
// Per block: compute the 36x36 h256 patch this 128x128 output tile needs
// (from a 22x22 h128 patch + cam256), entirely in smem, then do the
// specialized 4x upsample with a rolling-register-window vertical pass.
__global__ void __launch_bounds__(256, 8) up34_kernel(
    const float* __restrict__ h128, const float* __restrict__ cam256,
    const float* __restrict__ w3, const float* __restrict__ b3,
    float* __restrict__ out)
{
    constexpr int TILE = 128, OUT = 1024;
    constexpr int IT = 36;             // h256 patch edge
    constexpr int HP = 128;            // hmem pitch
    constexpr int PT = 22;             // h128 patch edge

    __shared__ __align__(16) float  raw [IT * IT];     // h256 patch
    __shared__ __align__(16) float  hmem[IT * HP];     // 4x horizontal buffer
    __shared__ __align__(16) float4 wxs[TILE];
    __shared__ __align__(16) float4 wys[TILE];

    // stage-3 scratch aliased into hmem (dead before hmem's first real use)
    struct S3 {
        float  p128[PT * PT];
        float  t3  [PT * IT];
        float4 w3x [IT];
        float4 w3y [IT];
        int    j3x [IT];
        int    j3y [IT];
    };
    S3& s3 = *reinterpret_cast<S3*>(hmem);

    const int tx0 = blockIdx.x * TILE;
    const int ty0 = blockIdx.y * TILE;
    const int b   = blockIdx.z;
    const int ix0 = tx0 / 4 - 2;       // even, >= -2
    const int iy0 = ty0 / 4 - 2;
    const int hx0 = ix0 / 2 - 2;       // h128 patch origin
    const int hy0 = iy0 / 2 - 2;
    const int t = threadIdx.x;

    // ---- per-block weight tables ----
    {
        float w[4];
        if (t < TILE) {                       // 4x column weights
            cubic_taps<4>(tx0 + t, 256, w);
            wxs[t] = make_float4(w[0], w[1], w[2], w[3]);
        } else {                              // 4x row weights
            int r = t - TILE;
            cubic_taps<4>(ty0 + r, 256, w);
            wys[r] = make_float4(w[0], w[1], w[2], w[3]);
        }
        if (t < IT) {                         // stage-3 column weights
            int gx = min(max(ix0 + t, 0), 255);
            int j0 = cubic_taps<2>(gx, 128, w);
            s3.w3x[t] = make_float4(w[0], w[1], w[2], w[3]);
            s3.j3x[t] = j0 - hx0;             // in [0, 18]
        } else if (t < 2 * IT) {              // stage-3 row weights
            int r = t - IT;
            int gy = min(max(iy0 + r, 0), 255);
            int j0 = cubic_taps<2>(gy, 128, w);
            s3.w3y[r] = make_float4(w[0], w[1], w[2], w[3]);
            s3.j3y[r] = j0 - hy0;
        }
    }

    // ---- load h128 patch (clamped; OOB taps carry zero weight) ----
    const float* h128b = h128 + (size_t)b * 128 * 128;
    for (int idx = t; idx < PT * PT; idx += 256) {
        int r = idx / PT, c = idx % PT;
        int gr = min(max(hy0 + r, 0), 127);
        int gc = min(max(hx0 + c, 0), 127);
        s3.p128[idx] = h128b[gr * 128 + gc];
    }
    __syncthreads();

    // ---- stage-3 horizontal: 22 rows x 36 out-cols ----
    for (int idx = t; idx < PT * IT; idx += 256) {
        int r = idx / IT, c = idx % IT;
        const float4 w = s3.w3x[c];
        const float* rp = &s3.p128[r * PT + s3.j3x[c]];
        s3.t3[idx] = w.x*rp[0] + w.y*rp[1] + w.z*rp[2] + w.w*rp[3];
    }
    __syncthreads();

    // ---- stage-3 vertical + conv/ReLU with cam256 -> raw (h256 patch) ----
    {
        const float fw0 = w3[0], fw1 = w3[1], fb = b3[0];
        const float* camb = cam256 + (size_t)b * 256 * 256;
        for (int idx = t; idx < IT * IT; idx += 256) {
            int r = idx / IT, c = idx % IT;
            const float4 w = s3.w3y[r];
            const float* cp = &s3.t3[s3.j3y[r] * IT + c];
            float up = w.x*cp[0] + w.y*cp[IT] + w.z*cp[2*IT] + w.w*cp[3*IT];
            int gy = min(max(iy0 + r, 0), 255);
            int gx = min(max(ix0 + c, 0), 255);
            raw[idx] = fmaxf(fw0 * up + fw1 * camb[gy * 256 + gx] + fb, 0.0f);
        }
    }
    __syncthreads();   // raw ready; s3 region (hmem) now dead

    // ---- 4x horizontal: 4 consecutive out-cols from 5 inputs ----
    {
        const int cg = t & 31;
        const int r0 = t >> 5;
        const float4 wA = wxs[4*cg+0];
        const float4 wB = wxs[4*cg+1];
        const float4 wC = wxs[4*cg+2];
        const float4 wD = wxs[4*cg+3];
        for (int r = r0; r < IT; r += 8) {
            const float* rp = &raw[r * IT + cg];
            float a0 = rp[0], a1 = rp[1], a2 = rp[2], a3 = rp[3], a4 = rp[4];
            float4 v;
            v.x = wA.x*a0 + wA.y*a1 + wA.z*a2 + wA.w*a3;   // phase 0
            v.y = wB.x*a0 + wB.y*a1 + wB.z*a2 + wB.w*a3;   // phase 1
            v.z = wC.x*a1 + wC.y*a2 + wC.z*a3 + wC.w*a4;   // phase 2
            v.w = wD.x*a1 + wD.y*a2 + wD.z*a3 + wD.w*a4;   // phase 3
            *(float4*)&hmem[r * HP + 4*cg] = v;
        }
    }
    __syncthreads();

    // ---- 4x vertical: rolling 5-register window over 4 consecutive groups
    // thread (c4, s): output rows 16s..16s+15, cols tx0+4*c4..+3.
    // hmem rows 4s..4s+7 each loaded exactly once.
    {
        const int c4 = t & 31;
        const int s  = t >> 5;
        const int cc = 4 * c4;
        float* outb = out + (size_t)(gridDim.z - 1 - b) * OUT * OUT;
        const float* hb = &hmem[cc];
        float* op = &outb[(size_t)(ty0 + 16*s) * OUT + tx0 + cc];
        const float4* wy = &wys[16*s];

        float4 r0 = *(const float4*)&hb[(4*s+0) * HP];
        float4 r1 = *(const float4*)&hb[(4*s+1) * HP];
        float4 r2 = *(const float4*)&hb[(4*s+2) * HP];
        float4 r3 = *(const float4*)&hb[(4*s+3) * HP];
        float4 r4 = *(const float4*)&hb[(4*s+4) * HP];

#define EMIT(WI, A, B, C, D, RO)                                          \
        {                                                                 \
            const float4 w = wy[WI];                                      \
            float4 v;                                                     \
            v.x = w.x*A.x + w.y*B.x + w.z*C.x + w.w*D.x;                  \
            v.y = w.x*A.y + w.y*B.y + w.z*C.y + w.w*D.y;                  \
            v.z = w.x*A.z + w.y*B.z + w.z*C.z + w.w*D.z;                  \
            v.w = w.x*A.w + w.y*B.w + w.z*C.w + w.w*D.w;                  \
            __stcs((float4*)(op + (size_t)(RO) * OUT), v);                \
        }
        // group 4s
        EMIT(0,  r0, r1, r2, r3, 0)
        EMIT(1,  r0, r1, r2, r3, 1)
        EMIT(2,  r1, r2, r3, r4, 2)
        EMIT(3,  r1, r2, r3, r4, 3)
        r0 = *(const float4*)&hb[(4*s+5) * HP];
        // group 4s+1
        EMIT(4,  r1, r2, r3, r4, 4)
        EMIT(5,  r1, r2, r3, r4, 5)
        EMIT(6,  r2, r3, r4, r0, 6)
        EMIT(7,  r2, r3, r4, r0, 7)
        r1 = *(const float4*)&hb[(4*s+6) * HP];
        // group 4s+2
        EMIT(8,  r2, r3, r4, r0, 8)
        EMIT(9,  r2, r3, r4, r0, 9)
        EMIT(10, r3, r4, r0, r1, 10)
        EMIT(11, r3, r4, r0, r1, 11)
        r2 = *(const float4*)&hb[(4*s+7) * HP];
        // group 4s+3
        EMIT(12, r3, r4, r0, r1, 12)
        EMIT(13, r3, r4, r0, r1, 13)
        EMIT(14, r4, r0, r1, r2, 14)
        EMIT(15, r4, r0, r1, r2, 15)
#undef EMIT
    }
}

extern "C" void kernel_launch(void* const* d_in, const int* in_sizes, int n_in,
                              void* d_out, int out_size)
{
    (void)in_sizes; (void)n_in; (void)out_size;
    const float* cam256 = (const float*)d_in[0];
    const float* cam128 = (const float*)d_in[1];
    const float* cam64  = (const float*)d_in[2];
    const float* cam32  = (const float*)d_in[3];
    const float* w1 = (const float*)d_in[4];
    const float* b1 = (const float*)d_in[5];
    const float* w2 = (const float*)d_in[6];
    const float* b2 = (const float*)d_in[7];
    const float* w3 = (const float*)d_in[8];
    const float* b3 = (const float*)d_in[9];
    float* out = (float*)d_out;

    float *h64, *h128;
    cudaGetSymbolAddress((void**)&h64,  g_h64);
    cudaGetSymbolAddress((void**)&h128, g_h128);

    // stage 1: 32 -> 64, fuse cam_64
    up2_kernel<32><<<dim3(2, 2, 64), 256>>>(cam32, 32, cam64, w1, b1, h64);
    // stage 2: 64 -> 128, fuse cam_128
    up2_kernel<32><<<dim3(4, 4, 64), 256>>>(h64, 64, cam128, w2, b2, h128);
    // fused stage 3 + 4: h128 -> (h256 in smem) -> 1024x1024, batch-flipped
    up34_kernel<<<dim3(8, 8, 64), 256>>>(h128, cam256, w3, b3, out);
}

// round 5
// speedup vs baseline: 1.8705x; 1.0523x over previous
#include <cuda_runtime.h>
#include <math.h>

// Keys cubic kernel, a = -0.5 (matches jax.image.resize method='cubic').
__device__ __forceinline__ float keys_w(float d) {
    d = fabsf(d);
    if (d <= 1.0f) return (1.5f * d - 2.5f) * d * d + 1.0f;
    if (d <  2.0f) return ((-0.5f * d + 2.5f) * d - 4.0f) * d + 2.0f;
    return 0.0f;
}

// jax semantics: x = (i+0.5)*in/out - 0.5; taps floor(x)-1 .. floor(x)+2;
// out-of-range taps dropped and the remaining weights renormalized.
template <int SCALE>
__device__ __forceinline__ int cubic_taps(int i, int in_size, float w[4]) {
    const float inv = 1.0f / (float)SCALE;
    float x = ((float)i + 0.5f) * inv - 0.5f;
    int fl = (int)floorf(x);
    int j0 = fl - 1;
    float s = 0.0f;
#pragma unroll
    for (int k = 0; k < 4; k++) {
        int j = j0 + k;
        float wk = keys_w(x - (float)j);
        if (j < 0 || j >= in_size) wk = 0.0f;
        w[k] = wk;
        s += wk;
    }
    float invs = 1.0f / s;
#pragma unroll
    for (int k = 0; k < 4; k++) w[k] *= invs;
    return j0;
}

// First tap index of the 2x-upsample stencil for output index g (exact, all g).
__device__ __forceinline__ int j2lo(int g) { return (g >> 1) - 2 + (g & 1); }

// ============ fully fused pyramid: cam32 -> ... -> 1024x1024, flipped =======
// Per 128x128 output tile, compute the whole ancestor chain in smem:
//   10x10 cam32 patch -> 14x14 h64 -> 22x22 h128 -> 36x36 h256 -> 4x upsample.
// OOB patch slots hold clamped (finite) values and always get weight 0 from
// the renormalized cubic weights, so the cascade is exact.
__global__ void __launch_bounds__(256, 8) fused_kernel(
    const float* __restrict__ cam32,  const float* __restrict__ cam64,
    const float* __restrict__ cam128, const float* __restrict__ cam256,
    const float* __restrict__ w1, const float* __restrict__ b1,
    const float* __restrict__ w2, const float* __restrict__ b2,
    const float* __restrict__ w3, const float* __restrict__ b3,
    float* __restrict__ out)
{
    constexpr int TILE = 128, OUT = 1024;
    constexpr int N3 = 36, N2 = 22, N1 = 14, N0 = 10;
    constexpr int HP = 128;

    __shared__ __align__(16) float  raw [N3 * N3];   // h256 patch
    __shared__ __align__(16) float  hmem[N3 * HP];   // 4x horizontal buffer
    __shared__ __align__(16) float4 wxs[TILE];
    __shared__ __align__(16) float4 wys[TILE];

    // pyramid scratch aliased into hmem (dead until the 4x horizontal pass)
    struct S {
        float  p32 [N0 * N0];
        float  t1  [N0 * N1];
        float  h64 [N1 * N1];
        float  t2  [N1 * N2];
        float  h128[N2 * N2];
        float  t3  [N2 * N3];
        float4 w1x[N1], w1y[N1];
        float4 w2x[N2], w2y[N2];
        float4 w3x[N3], w3y[N3];
        int j1x[N1], j1y[N1], j2x[N2], j2y[N2], j3x[N3], j3y[N3];
    };
    static_assert(sizeof(S) <= N3 * HP * 4, "scratch overflows hmem alias");
    S& s = *reinterpret_cast<S*>(hmem);

    const int tx0 = blockIdx.x * TILE;
    const int ty0 = blockIdx.y * TILE;
    const int b   = blockIdx.z;
    const int t   = threadIdx.x;

    const int ix0 = tx0 / 4 - 2,  iy0 = ty0 / 4 - 2;   // h256 patch origin
    const int hx0 = j2lo(ix0),    hy0 = j2lo(iy0);     // h128
    const int qx0 = j2lo(hx0),    qy0 = j2lo(hy0);     // h64
    const int px0 = j2lo(qx0),    py0 = j2lo(qy0);     // cam32

    // ---- stage-4 weight tables ----
    {
        float w[4];
        if (t < TILE) {
            cubic_taps<4>(tx0 + t, 256, w);
            wxs[t] = make_float4(w[0], w[1], w[2], w[3]);
        } else {
            cubic_taps<4>(ty0 + (t - TILE), 256, w);
            wys[t - TILE] = make_float4(w[0], w[1], w[2], w[3]);
        }
    }
    // ---- stage-1..3 weight tables (144 entries, one per thread) ----
    if (t < 2 * (N1 + N2 + N3)) {
        int e = t;
        float w[4];
        if (e < 2 * N1) {
            bool ya = e >= N1; int i = ya ? e - N1 : e;
            int g = min(max((ya ? qy0 : qx0) + i, 0), 63);
            int j0 = cubic_taps<2>(g, 32, w);
            float4 wv = make_float4(w[0], w[1], w[2], w[3]);
            if (ya) { s.w1y[i] = wv; s.j1y[i] = j0 - py0; }
            else    { s.w1x[i] = wv; s.j1x[i] = j0 - px0; }
        } else if (e < 2 * N1 + 2 * N2) {
            e -= 2 * N1;
            bool ya = e >= N2; int i = ya ? e - N2 : e;
            int g = min(max((ya ? hy0 : hx0) + i, 0), 127);
            int j0 = cubic_taps<2>(g, 64, w);
            float4 wv = make_float4(w[0], w[1], w[2], w[3]);
            if (ya) { s.w2y[i] = wv; s.j2y[i] = j0 - qy0; }
            else    { s.w2x[i] = wv; s.j2x[i] = j0 - qx0; }
        } else {
            e -= 2 * N1 + 2 * N2;
            bool ya = e >= N3; int i = ya ? e - N3 : e;
            int g = min(max((ya ? iy0 : ix0) + i, 0), 255);
            int j0 = cubic_taps<2>(g, 128, w);
            float4 wv = make_float4(w[0], w[1], w[2], w[3]);
            if (ya) { s.w3y[i] = wv; s.j3y[i] = j0 - hy0; }
            else    { s.w3x[i] = wv; s.j3x[i] = j0 - hx0; }
        }
    }

    // ---- cam32 patch (clamped) ----
    {
        const float* c32b = cam32 + (size_t)b * 32 * 32;
        for (int i = t; i < N0 * N0; i += 256) {
            int r = i / N0, c = i % N0;
            int gr = min(max(py0 + r, 0), 31);
            int gc = min(max(px0 + c, 0), 31);
            s.p32[i] = c32b[gr * 32 + gc];
        }
    }
    __syncthreads();

    // ---- stage 1 horizontal: N0 rows x N1 cols ----
    for (int i = t; i < N0 * N1; i += 256) {
        int r = i / N1, c = i % N1;
        const float4 w = s.w1x[c];
        const float* rp = &s.p32[r * N0 + s.j1x[c]];
        s.t1[i] = w.x*rp[0] + w.y*rp[1] + w.z*rp[2] + w.w*rp[3];
    }
    __syncthreads();

    // ---- stage 1 vertical + conv/ReLU with cam64 -> h64 ----
    {
        const float fa = w1[0], fcb = w1[1], fc = b1[0];
        const float* c64b = cam64 + (size_t)b * 64 * 64;
        for (int i = t; i < N1 * N1; i += 256) {
            int r = i / N1, c = i % N1;
            const float4 w = s.w1y[r];
            const float* cp = &s.t1[s.j1y[r] * N1 + c];
            float up = w.x*cp[0] + w.y*cp[N1] + w.z*cp[2*N1] + w.w*cp[3*N1];
            int gy = min(max(qy0 + r, 0), 63);
            int gx = min(max(qx0 + c, 0), 63);
            s.h64[i] = fmaxf(fa * up + fcb * c64b[gy * 64 + gx] + fc, 0.0f);
        }
    }
    __syncthreads();

    // ---- stage 2 horizontal: N1 rows x N2 cols ----
    for (int i = t; i < N1 * N2; i += 256) {
        int r = i / N2, c = i % N2;
        const float4 w = s.w2x[c];
        const float* rp = &s.h64[r * N1 + s.j2x[c]];
        s.t2[i] = w.x*rp[0] + w.y*rp[1] + w.z*rp[2] + w.w*rp[3];
    }
    __syncthreads();

    // ---- stage 2 vertical + conv/ReLU with cam128 -> h128 ----
    {
        const float fa = w2[0], fcb = w2[1], fc = b2[0];
        const float* c128b = cam128 + (size_t)b * 128 * 128;
        for (int i = t; i < N2 * N2; i += 256) {
            int r = i / N2, c = i % N2;
            const float4 w = s.w2y[r];
            const float* cp = &s.t2[s.j2y[r] * N2 + c];
            float up = w.x*cp[0] + w.y*cp[N2] + w.z*cp[2*N2] + w.w*cp[3*N2];
            int gy = min(max(hy0 + r, 0), 127);
            int gx = min(max(hx0 + c, 0), 127);
            s.h128[i] = fmaxf(fa * up + fcb * c128b[gy * 128 + gx] + fc, 0.0f);
        }
    }
    __syncthreads();

    // ---- stage 3 horizontal: N2 rows x N3 cols ----
    for (int i = t; i < N2 * N3; i += 256) {
        int r = i / N3, c = i % N3;
        const float4 w = s.w3x[c];
        const float* rp = &s.h128[r * N2 + s.j3x[c]];
        s.t3[i] = w.x*rp[0] + w.y*rp[1] + w.z*rp[2] + w.w*rp[3];
    }
    __syncthreads();

    // ---- stage 3 vertical + conv/ReLU with cam256 -> raw (h256 patch) ----
    {
        const float fa = w3[0], fcb = w3[1], fc = b3[0];
        const float* c256b = cam256 + (size_t)b * 256 * 256;
        for (int i = t; i < N3 * N3; i += 256) {
            int r = i / N3, c = i % N3;
            const float4 w = s.w3y[r];
            const float* cp = &s.t3[s.j3y[r] * N3 + c];
            float up = w.x*cp[0] + w.y*cp[N3] + w.z*cp[2*N3] + w.w*cp[3*N3];
            int gy = min(max(iy0 + r, 0), 255);
            int gx = min(max(ix0 + c, 0), 255);
            raw[i] = fmaxf(fa * up + fcb * c256b[gy * 256 + gx] + fc, 0.0f);
        }
    }
    __syncthreads();   // raw ready; scratch S (hmem) now dead

    // ---- 4x horizontal: 4 consecutive out-cols from 5 inputs ----
    {
        const int cg = t & 31;
        const int r0 = t >> 5;
        const float4 wA = wxs[4*cg+0];
        const float4 wB = wxs[4*cg+1];
        const float4 wC = wxs[4*cg+2];
        const float4 wD = wxs[4*cg+3];
        for (int r = r0; r < N3; r += 8) {
            const float* rp = &raw[r * N3 + cg];
            float a0 = rp[0], a1 = rp[1], a2 = rp[2], a3 = rp[3], a4 = rp[4];
            float4 v;
            v.x = wA.x*a0 + wA.y*a1 + wA.z*a2 + wA.w*a3;   // phase 0
            v.y = wB.x*a0 + wB.y*a1 + wB.z*a2 + wB.w*a3;   // phase 1
            v.z = wC.x*a1 + wC.y*a2 + wC.z*a3 + wC.w*a4;   // phase 2
            v.w = wD.x*a1 + wD.y*a2 + wD.z*a3 + wD.w*a4;   // phase 3
            *(float4*)&hmem[r * HP + 4*cg] = v;
        }
    }
    __syncthreads();

    // ---- 4x vertical: rolling 5-register window over 4 consecutive groups
    {
        const int c4 = t & 31;
        const int sv = t >> 5;
        const int cc = 4 * c4;
        float* outb = out + (size_t)(gridDim.z - 1 - b) * OUT * OUT;
        const float* hb = &hmem[cc];
        float* op = &outb[(size_t)(ty0 + 16*sv) * OUT + tx0 + cc];
        const float4* wy = &wys[16*sv];

        float4 r0 = *(const float4*)&hb[(4*sv+0) * HP];
        float4 r1 = *(const float4*)&hb[(4*sv+1) * HP];
        float4 r2 = *(const float4*)&hb[(4*sv+2) * HP];
        float4 r3 = *(const float4*)&hb[(4*sv+3) * HP];
        float4 r4 = *(const float4*)&hb[(4*sv+4) * HP];

#define EMIT(WI, A, B, C, D, RO)                                          \
        {                                                                 \
            const float4 w = wy[WI];                                      \
            float4 v;                                                     \
            v.x = w.x*A.x + w.y*B.x + w.z*C.x + w.w*D.x;                  \
            v.y = w.x*A.y + w.y*B.y + w.z*C.y + w.w*D.y;                  \
            v.z = w.x*A.z + w.y*B.z + w.z*C.z + w.w*D.z;                  \
            v.w = w.x*A.w + w.y*B.w + w.z*C.w + w.w*D.w;                  \
            __stcs((float4*)(op + (size_t)(RO) * OUT), v);                \
        }
        EMIT(0,  r0, r1, r2, r3, 0)
        EMIT(1,  r0, r1, r2, r3, 1)
        EMIT(2,  r1, r2, r3, r4, 2)
        EMIT(3,  r1, r2, r3, r4, 3)
        r0 = *(const float4*)&hb[(4*sv+5) * HP];
        EMIT(4,  r1, r2, r3, r4, 4)
        EMIT(5,  r1, r2, r3, r4, 5)
        EMIT(6,  r2, r3, r4, r0, 6)
        EMIT(7,  r2, r3, r4, r0, 7)
        r1 = *(const float4*)&hb[(4*sv+6) * HP];
        EMIT(8,  r2, r3, r4, r0, 8)
        EMIT(9,  r2, r3, r4, r0, 9)
        EMIT(10, r3, r4, r0, r1, 10)
        EMIT(11, r3, r4, r0, r1, 11)
        r2 = *(const float4*)&hb[(4*sv+7) * HP];
        EMIT(12, r3, r4, r0, r1, 12)
        EMIT(13, r3, r4, r0, r1, 13)
        EMIT(14, r4, r0, r1, r2, 14)
        EMIT(15, r4, r0, r1, r2, 15)
#undef EMIT
    }
}

extern "C" void kernel_launch(void* const* d_in, const int* in_sizes, int n_in,
                              void* d_out, int out_size)
{
    (void)in_sizes; (void)n_in; (void)out_size;
    const float* cam256 = (const float*)d_in[0];
    const float* cam128 = (const float*)d_in[1];
    const float* cam64  = (const float*)d_in[2];
    const float* cam32  = (const float*)d_in[3];
    const float* w1 = (const float*)d_in[4];
    const float* b1 = (const float*)d_in[5];
    const float* w2 = (const float*)d_in[6];
    const float* b2 = (const float*)d_in[7];
    const float* w3 = (const float*)d_in[8];
    const float* b3 = (const float*)d_in[9];
    float* out = (float*)d_out;

    fused_kernel<<<dim3(8, 8, 64), 256>>>(
        cam32, cam64, cam128, cam256, w1, b1, w2, b2, w3, b3, out);
}